// round 8
// baseline (speedup 1.0000x reference)
#include <cuda_runtime.h>
#include <math.h>
#include <stdint.h>

#define N_TOK 4096
#define H_DIM 1024
#define F_DIM 4096
#define N_EXP 8

#define BM 128
#define BN 256
#define BK 32
#define NTHREADS 512
#define NSTAGE 3
#define TILES_PER_E 32

#define AS_STRIDE 36     // bank = (4*gid+tig) mod 32 -> all 32 distinct
#define BS_STRIDE 264    // bank = (8*tig+gid) mod 32 -> all 32 distinct
#define A_STAGE_W (BM * AS_STRIDE)          // 4608 words
#define B_STAGE_W (BK * BS_STRIDE)          // 8448 words
#define SMEM_BYTES (512 + NSTAGE * A_STAGE_W * 4 + NSTAGE * B_STAGE_W * 4)  // 157184

// Routing state + scratch (allocation-free: __device__ globals).
__device__ int      g_cnt[N_EXP];
__device__ int      g_off[N_EXP];
__device__ int      g_tok[N_EXP * N_TOK];
__device__ float    g_gw [N_EXP * N_TOK];
__device__ unsigned g_xt[(size_t)N_TOK * H_DIM];        // x as tf32 bits
__device__ unsigned g_h[(size_t)9216 * F_DIM];          // gelu(h) as tf32 bits

__device__ __forceinline__ uint32_t f2tf32(float f) {
    uint32_t r;
    asm("cvt.rna.tf32.f32 %0, %1;" : "=r"(r) : "f"(f));
    return r;
}
__device__ __forceinline__ void mma_tf32(float c[4],
                                         uint32_t a0, uint32_t a1, uint32_t a2, uint32_t a3,
                                         uint32_t b0, uint32_t b1) {
    asm volatile(
        "mma.sync.aligned.m16n8k8.row.col.f32.tf32.tf32.f32 "
        "{%0,%1,%2,%3}, {%4,%5,%6,%7}, {%8,%9}, {%0,%1,%2,%3};\n"
        : "+f"(c[0]), "+f"(c[1]), "+f"(c[2]), "+f"(c[3])
        : "r"(a0), "r"(a1), "r"(a2), "r"(a3), "r"(b0), "r"(b1));
}
#define CP_ASYNC16(dst, src) \
    asm volatile("cp.async.cg.shared.global [%0], [%1], 16;" :: "r"(dst), "l"(src) : "memory")
#define CP_COMMIT() asm volatile("cp.async.commit_group;" ::: "memory")
#define CP_WAIT1()  asm volatile("cp.async.wait_group 1;" ::: "memory")

__device__ __forceinline__ float gelu_exact(float v) {
    return 0.5f * v * (1.0f + erff(v * 0.70710678118654752f));
}

// ---------------- small kernels ----------------
__global__ void zero_kernel(float* __restrict__ out, int n) {
    int i = blockIdx.x * blockDim.x + threadIdx.x;
    if (i < N_EXP) g_cnt[i] = 0;
    int stride = gridDim.x * blockDim.x;
    for (int j = i; j < n; j += stride) out[j] = 0.0f;
}

__global__ void xconv_kernel(const float* __restrict__ x) {
    int i = blockIdx.x * blockDim.x + threadIdx.x;
    float4 v = reinterpret_cast<const float4*>(x)[i];
    uint4 o = {f2tf32(v.x), f2tf32(v.y), f2tf32(v.z), f2tf32(v.w)};
    reinterpret_cast<uint4*>(g_xt)[i] = o;
}

__global__ void gate_kernel(const float* __restrict__ x,
                            const float* __restrict__ Wg,
                            const float* __restrict__ bg) {
    int warp = threadIdx.x >> 5, lane = threadIdx.x & 31;
    int n = blockIdx.x * (blockDim.x >> 5) + warp;
    if (n >= N_TOK) return;
    float acc[N_EXP];
#pragma unroll
    for (int e = 0; e < N_EXP; e++) acc[e] = 0.0f;
    const float* xr = x + (size_t)n * H_DIM;
    for (int h = lane; h < H_DIM; h += 32) {
        float xv = xr[h];
        const float4 w0 = *reinterpret_cast<const float4*>(Wg + h * N_EXP);
        const float4 w1 = *reinterpret_cast<const float4*>(Wg + h * N_EXP + 4);
        acc[0] += xv * w0.x; acc[1] += xv * w0.y; acc[2] += xv * w0.z; acc[3] += xv * w0.w;
        acc[4] += xv * w1.x; acc[5] += xv * w1.y; acc[6] += xv * w1.z; acc[7] += xv * w1.w;
    }
#pragma unroll
    for (int e = 0; e < N_EXP; e++)
#pragma unroll
        for (int o = 16; o > 0; o >>= 1) acc[e] += __shfl_xor_sync(0xffffffffu, acc[e], o);
    if (lane == 0) {
        float p[N_EXP], m = -1e30f, s = 0.0f;
#pragma unroll
        for (int e = 0; e < N_EXP; e++) { p[e] = acc[e] + bg[e]; m = fmaxf(m, p[e]); }
#pragma unroll
        for (int e = 0; e < N_EXP; e++) { p[e] = expf(p[e] - m); s += p[e]; }
        float inv = 1.0f / s;
#pragma unroll
        for (int e = 0; e < N_EXP; e++) p[e] *= inv;
        int i0 = 0;
#pragma unroll
        for (int e = 1; e < N_EXP; e++) if (p[e] > p[i0]) i0 = e;
        int i1 = (i0 == 0) ? 1 : 0;
#pragma unroll
        for (int e = 0; e < N_EXP; e++) if (e != i0 && p[e] > p[i1]) i1 = e;
        int p0 = atomicAdd(&g_cnt[i0], 1);
        g_tok[i0 * N_TOK + p0] = n;  g_gw[i0 * N_TOK + p0] = p[i0];
        int p1 = atomicAdd(&g_cnt[i1], 1);
        g_tok[i1 * N_TOK + p1] = n;  g_gw[i1 * N_TOK + p1] = p[i1];
    }
}

__global__ void offsets_kernel() {
    if (threadIdx.x == 0 && blockIdx.x == 0) {
        int off = 0;
        for (int e = 0; e < N_EXP; e++) {
            g_off[e] = off;
            off += ((g_cnt[e] + BM - 1) / BM) * BM;
        }
    }
}

// ---------------------------------------------------------------------------
// GEMM core: 16 warps of 64x32; A tf32-bits in smem, B fp32 (cvt at fragment)
// ---------------------------------------------------------------------------
#define DECLARE_TILE_CTX() \
    int tid = threadIdx.x, warp = tid >> 5, lane = tid & 31; \
    int gid = lane >> 2, tig = lane & 3; \
    int wm = (warp >> 3) * 64, wn = (warp & 7) * 32; \
    float acc[4][4][4]; \
    _Pragma("unroll") for (int mf = 0; mf < 4; mf++) \
    _Pragma("unroll") for (int nf = 0; nf < 4; nf++) \
    _Pragma("unroll") for (int r = 0; r < 4; r++) acc[mf][nf][r] = 0.0f;

#define COMPUTE_KTILE(Ast, Bst) do { \
    _Pragma("unroll") \
    for (int ks = 0; ks < 4; ks++) { \
        int k = ks * 8; \
        uint32_t af[4][4], bf[4][2]; \
        _Pragma("unroll") \
        for (int mf = 0; mf < 4; mf++) { \
            int m = wm + mf * 16 + gid; \
            af[mf][0] = (Ast)[m * AS_STRIDE + k + tig]; \
            af[mf][1] = (Ast)[(m + 8) * AS_STRIDE + k + tig]; \
            af[mf][2] = (Ast)[m * AS_STRIDE + k + tig + 4]; \
            af[mf][3] = (Ast)[(m + 8) * AS_STRIDE + k + tig + 4]; \
        } \
        _Pragma("unroll") \
        for (int nf = 0; nf < 4; nf++) { \
            int n = wn + nf * 8 + gid; \
            bf[nf][0] = f2tf32((Bst)[(k + tig) * BS_STRIDE + n]); \
            bf[nf][1] = f2tf32((Bst)[(k + tig + 4) * BS_STRIDE + n]); \
        } \
        _Pragma("unroll") \
        for (int mf = 0; mf < 4; mf++) \
        _Pragma("unroll") \
        for (int nf = 0; nf < 4; nf++) \
            mma_tf32(acc[mf][nf], af[mf][0], af[mf][1], af[mf][2], af[mf][3], \
                     bf[nf][0], bf[nf][1]); \
    } } while (0)

// ---------------------------------------------------------------------------
// ffn1: g_h = tf32(gelu(X_gathered @ W1[e] + b1[e]))   K = H_DIM
// ---------------------------------------------------------------------------
__global__ __launch_bounds__(NTHREADS, 1) void ffn1_kernel(
    const float* __restrict__ W1,
    const float* __restrict__ b1) {
    extern __shared__ char dsm[];
    int* toks     = (int*)dsm;
    unsigned* As  = (unsigned*)(dsm + 512);
    float* Bs     = (float*)(dsm + 512 + NSTAGE * A_STAGE_W * 4);

    int e    = blockIdx.y >> 5;
    int tile = blockIdx.y & 31;
    int row0 = tile * BM;
    int cnt  = g_cnt[e];
    if (row0 >= cnt) return;
    int off  = g_off[e];
    int col0 = blockIdx.x * BN;
    const float* B = W1 + (size_t)e * H_DIM * F_DIM;

    DECLARE_TILE_CTX();

    if (tid < BM) {
        int r = row0 + tid; if (r >= cnt) r = cnt - 1;
        toks[tid] = g_tok[e * N_TOK + r];
    }
    __syncthreads();

    // cp.async slots: A 1024 f4-slots (2/thread), B 2048 f4-slots (4/thread)
    int a_rw = tid >> 3, a_c4 = tid & 7;           // + 64 rows for i=1
    uint32_t a_dst[2]; const unsigned* a_src[2];
#pragma unroll
    for (int i = 0; i < 2; i++) {
        int rw = a_rw + i * 64;
        a_dst[i] = (uint32_t)__cvta_generic_to_shared(As + rw * AS_STRIDE + a_c4 * 4);
        a_src[i] = g_xt + (size_t)toks[rw] * H_DIM + a_c4 * 4;
    }
    int b_k = tid >> 6, b_n4 = tid & 63;           // + 8 k-rows per i
    uint32_t b_dst[4]; const float* b_src[4];
#pragma unroll
    for (int i = 0; i < 4; i++) {
        int kk = b_k + i * 8;
        b_dst[i] = (uint32_t)__cvta_generic_to_shared(Bs + kk * BS_STRIDE + b_n4 * 4);
        b_src[i] = B + (size_t)kk * F_DIM + col0 + b_n4 * 4;
    }

#define FILL1(st, k0) do { \
    _Pragma("unroll") for (int i = 0; i < 2; i++) \
        CP_ASYNC16(a_dst[i] + (st) * (A_STAGE_W * 4), a_src[i] + (k0)); \
    _Pragma("unroll") for (int i = 0; i < 4; i++) \
        CP_ASYNC16(b_dst[i] + (st) * (B_STAGE_W * 4), b_src[i] + (size_t)(k0) * F_DIM); \
    CP_COMMIT(); } while (0)

    FILL1(0, 0);
    FILL1(1, BK);
    const int NKT = H_DIM / BK;
#pragma unroll 1
    for (int kt = 0; kt < NKT; kt++) {
        CP_WAIT1();
        __syncthreads();
        int nk = kt + 2;
        if (nk < NKT) {
            int st = nk % NSTAGE;
            FILL1(st, nk * BK);
        }
        int cs = kt % NSTAGE;
        const unsigned* Ast = As + cs * A_STAGE_W;
        const float*    Bst = Bs + cs * B_STAGE_W;
        COMPUTE_KTILE(Ast, Bst);
    }

    // epilogue: bias + exact gelu -> g_h (tf32 bits)
#pragma unroll
    for (int mf = 0; mf < 4; mf++) {
#pragma unroll
        for (int r2 = 0; r2 < 2; r2++) {
            int m = wm + mf * 16 + gid + r2 * 8;
            unsigned* hrow = g_h + (size_t)(off + row0 + m) * F_DIM + col0;
#pragma unroll
            for (int nf = 0; nf < 4; nf++) {
                int c = wn + nf * 8 + tig * 2;
                float v0 = acc[mf][nf][r2 * 2 + 0] + b1[e * F_DIM + col0 + c];
                float v1 = acc[mf][nf][r2 * 2 + 1] + b1[e * F_DIM + col0 + c + 1];
                uint2 g = {f2tf32(gelu_exact(v0)), f2tf32(gelu_exact(v1))};
                *reinterpret_cast<uint2*>(hrow + c) = g;
            }
        }
    }
}

// ---------------------------------------------------------------------------
// ffn2: out[token] += gw * (h @ W2[e] + b2[e])   K = F_DIM
// ---------------------------------------------------------------------------
__global__ __launch_bounds__(NTHREADS, 1) void ffn2_kernel(
    const float* __restrict__ W2,
    const float* __restrict__ b2,
    float* __restrict__ out) {
    extern __shared__ char dsm[];
    unsigned* As  = (unsigned*)(dsm + 512);
    float* Bs     = (float*)(dsm + 512 + NSTAGE * A_STAGE_W * 4);

    int e    = blockIdx.y >> 5;
    int tile = blockIdx.y & 31;
    int row0 = tile * BM;
    int cnt  = g_cnt[e];
    if (row0 >= cnt) return;
    int off  = g_off[e];
    int col0 = blockIdx.x * BN;
    const float* B = W2 + (size_t)e * F_DIM * H_DIM;
    const unsigned* A = g_h + (size_t)(off + row0) * F_DIM;

    DECLARE_TILE_CTX();

    int a_rw = tid >> 3, a_c4 = tid & 7;
    uint32_t a_dst[2]; const unsigned* a_src[2];
#pragma unroll
    for (int i = 0; i < 2; i++) {
        int rw = a_rw + i * 64;
        a_dst[i] = (uint32_t)__cvta_generic_to_shared(As + rw * AS_STRIDE + a_c4 * 4);
        a_src[i] = A + (size_t)rw * F_DIM + a_c4 * 4;
    }
    int b_k = tid >> 6, b_n4 = tid & 63;
    uint32_t b_dst[4]; const float* b_src[4];
#pragma unroll
    for (int i = 0; i < 4; i++) {
        int kk = b_k + i * 8;
        b_dst[i] = (uint32_t)__cvta_generic_to_shared(Bs + kk * BS_STRIDE + b_n4 * 4);
        b_src[i] = B + (size_t)kk * H_DIM + col0 + b_n4 * 4;
    }

#define FILL2(st, k0) do { \
    _Pragma("unroll") for (int i = 0; i < 2; i++) \
        CP_ASYNC16(a_dst[i] + (st) * (A_STAGE_W * 4), a_src[i] + (k0)); \
    _Pragma("unroll") for (int i = 0; i < 4; i++) \
        CP_ASYNC16(b_dst[i] + (st) * (B_STAGE_W * 4), b_src[i] + (size_t)(k0) * H_DIM); \
    CP_COMMIT(); } while (0)

    FILL2(0, 0);
    FILL2(1, BK);
    const int NKT = F_DIM / BK;
#pragma unroll 1
    for (int kt = 0; kt < NKT; kt++) {
        CP_WAIT1();
        __syncthreads();
        int nk = kt + 2;
        if (nk < NKT) {
            int st = nk % NSTAGE;
            FILL2(st, nk * BK);
        }
        int cs = kt % NSTAGE;
        const unsigned* Ast = As + cs * A_STAGE_W;
        const float*    Bst = Bs + cs * B_STAGE_W;
        COMPUTE_KTILE(Ast, Bst);
    }

    // epilogue: bias, gate weight, atomic scatter
#pragma unroll
    for (int mf = 0; mf < 4; mf++) {
#pragma unroll
        for (int r2 = 0; r2 < 2; r2++) {
            int m = wm + mf * 16 + gid + r2 * 8;
            int r = row0 + m;
            if (r < cnt) {
                int   token = g_tok[e * N_TOK + r];
                float gw    = g_gw [e * N_TOK + r];
                float* orow = out + (size_t)token * H_DIM + col0;
#pragma unroll
                for (int nf = 0; nf < 4; nf++) {
                    int c = wn + nf * 8 + tig * 2;
                    float v0 = acc[mf][nf][r2 * 2 + 0] + b2[e * H_DIM + col0 + c];
                    float v1 = acc[mf][nf][r2 * 2 + 1] + b2[e * H_DIM + col0 + c + 1];
                    atomicAdd(orow + c,     gw * v0);
                    atomicAdd(orow + c + 1, gw * v1);
                }
            }
        }
    }
}

extern "C" void kernel_launch(void* const* d_in, const int* in_sizes, int n_in,
                              void* d_out, int out_size) {
    const float* x  = (const float*)d_in[0];
    const float* W1 = (const float*)d_in[1];
    const float* b1 = (const float*)d_in[2];
    const float* W2 = (const float*)d_in[3];
    const float* b2 = (const float*)d_in[4];
    const float* Wg = (const float*)d_in[5];
    const float* bg = (const float*)d_in[6];
    float* out = (float*)d_out;

    cudaFuncSetAttribute(ffn1_kernel, cudaFuncAttributeMaxDynamicSharedMemorySize, SMEM_BYTES);
    cudaFuncSetAttribute(ffn2_kernel, cudaFuncAttributeMaxDynamicSharedMemorySize, SMEM_BYTES);

    zero_kernel<<<1024, 256>>>(out, out_size);
    xconv_kernel<<<(N_TOK * H_DIM / 4) / 256, 256>>>(x);
    gate_kernel<<<N_TOK / 8, 256>>>(x, Wg, bg);
    offsets_kernel<<<1, 1>>>();
    ffn1_kernel<<<dim3(F_DIM / BN, N_EXP * TILES_PER_E), NTHREADS, SMEM_BYTES>>>(W1, b1);
    ffn2_kernel<<<dim3(H_DIM / BN, N_EXP * TILES_PER_E), NTHREADS, SMEM_BYTES>>>(W2, b2, out);
}

// round 9
// speedup vs baseline: 1.5307x; 1.5307x over previous
#include <cuda_runtime.h>
#include <cuda_fp16.h>
#include <math.h>
#include <stdint.h>

#define N_TOK 4096
#define H_DIM 1024
#define F_DIM 4096
#define N_EXP 8

#define BM 128
#define BN 256
#define BK 32
#define NTHREADS 256
#define NSTAGE 3
#define TILES_PER_E 32

#define AH_STRIDE 40      // halfs: 32 + 8 pad -> 80B rows; 80*r mod 128 distinct over 8 rows
#define BH_STRIDE 264     // halfs: 256 + 8 pad -> 528B rows; 528*k mod 128 distinct over 8 rows
#define A_STAGE_B (BM * AH_STRIDE * 2)   // 10240 B
#define B_STAGE_B (BK * BH_STRIDE * 2)   // 16896 B
#define SMEM_BYTES (512 + NSTAGE * (A_STAGE_B + B_STAGE_B))   // 81920

// Routing state + scratch (allocation-free: __device__ globals).
__device__ int    g_cnt[N_EXP];
__device__ int    g_off[N_EXP];
__device__ int    g_tok[N_EXP * N_TOK];
__device__ float  g_gw [N_EXP * N_TOK];
__device__ __half g_xh [(size_t)N_TOK * H_DIM];               // x  fp16
__device__ __half g_W1h[(size_t)N_EXP * H_DIM * F_DIM];       // W1 fp16 [E][H][F]
__device__ __half g_W2h[(size_t)N_EXP * F_DIM * H_DIM];       // W2 fp16 [E][F][H]
__device__ __half g_h  [(size_t)9216 * F_DIM];                // gelu(h) fp16

__device__ __forceinline__ void mma_f16(float c[4],
                                        uint32_t a0, uint32_t a1, uint32_t a2, uint32_t a3,
                                        uint32_t b0, uint32_t b1) {
    asm volatile(
        "mma.sync.aligned.m16n8k16.row.col.f32.f16.f16.f32 "
        "{%0,%1,%2,%3}, {%4,%5,%6,%7}, {%8,%9}, {%0,%1,%2,%3};\n"
        : "+f"(c[0]), "+f"(c[1]), "+f"(c[2]), "+f"(c[3])
        : "r"(a0), "r"(a1), "r"(a2), "r"(a3), "r"(b0), "r"(b1));
}
#define LDSM_X4(r, addr) \
    asm volatile("ldmatrix.sync.aligned.m8n8.x4.shared.b16 {%0,%1,%2,%3}, [%4];" \
        : "=r"((r)[0]), "=r"((r)[1]), "=r"((r)[2]), "=r"((r)[3]) : "r"(addr))
#define LDSM_X4_T(r, addr) \
    asm volatile("ldmatrix.sync.aligned.m8n8.x4.trans.shared.b16 {%0,%1,%2,%3}, [%4];" \
        : "=r"((r)[0]), "=r"((r)[1]), "=r"((r)[2]), "=r"((r)[3]) : "r"(addr))
#define CP_ASYNC16(dst, src) \
    asm volatile("cp.async.cg.shared.global [%0], [%1], 16;" :: "r"(dst), "l"(src) : "memory")
#define CP_COMMIT() asm volatile("cp.async.commit_group;" ::: "memory")
#define CP_WAIT1()  asm volatile("cp.async.wait_group 1;" ::: "memory")

__device__ __forceinline__ float gelu_exact(float v) {
    return 0.5f * v * (1.0f + erff(v * 0.70710678118654752f));
}

// ---------------- small kernels ----------------
__global__ void zero_kernel(float* __restrict__ out, int n) {
    int i = blockIdx.x * blockDim.x + threadIdx.x;
    if (i < N_EXP) g_cnt[i] = 0;
    int stride = gridDim.x * blockDim.x;
    for (int j = i; j < n; j += stride) out[j] = 0.0f;
}

__global__ void h16conv_kernel(const float* __restrict__ src, __half* __restrict__ dst) {
    size_t i = (size_t)blockIdx.x * blockDim.x + threadIdx.x;
    float4 v = reinterpret_cast<const float4*>(src)[i];
    __half2 h0 = __floats2half2_rn(v.x, v.y);
    __half2 h1 = __floats2half2_rn(v.z, v.w);
    uint2 o = {*reinterpret_cast<uint32_t*>(&h0), *reinterpret_cast<uint32_t*>(&h1)};
    reinterpret_cast<uint2*>(dst)[i] = o;
}

__global__ void gate_kernel(const float* __restrict__ x,
                            const float* __restrict__ Wg,
                            const float* __restrict__ bg) {
    int warp = threadIdx.x >> 5, lane = threadIdx.x & 31;
    int n = blockIdx.x * (blockDim.x >> 5) + warp;
    if (n >= N_TOK) return;
    float acc[N_EXP];
#pragma unroll
    for (int e = 0; e < N_EXP; e++) acc[e] = 0.0f;
    const float* xr = x + (size_t)n * H_DIM;
    for (int h = lane; h < H_DIM; h += 32) {
        float xv = xr[h];
        const float4 w0 = *reinterpret_cast<const float4*>(Wg + h * N_EXP);
        const float4 w1 = *reinterpret_cast<const float4*>(Wg + h * N_EXP + 4);
        acc[0] += xv * w0.x; acc[1] += xv * w0.y; acc[2] += xv * w0.z; acc[3] += xv * w0.w;
        acc[4] += xv * w1.x; acc[5] += xv * w1.y; acc[6] += xv * w1.z; acc[7] += xv * w1.w;
    }
#pragma unroll
    for (int e = 0; e < N_EXP; e++)
#pragma unroll
        for (int o = 16; o > 0; o >>= 1) acc[e] += __shfl_xor_sync(0xffffffffu, acc[e], o);
    if (lane == 0) {
        float p[N_EXP], m = -1e30f, s = 0.0f;
#pragma unroll
        for (int e = 0; e < N_EXP; e++) { p[e] = acc[e] + bg[e]; m = fmaxf(m, p[e]); }
#pragma unroll
        for (int e = 0; e < N_EXP; e++) { p[e] = expf(p[e] - m); s += p[e]; }
        float inv = 1.0f / s;
#pragma unroll
        for (int e = 0; e < N_EXP; e++) p[e] *= inv;
        int i0 = 0;
#pragma unroll
        for (int e = 1; e < N_EXP; e++) if (p[e] > p[i0]) i0 = e;
        int i1 = (i0 == 0) ? 1 : 0;
#pragma unroll
        for (int e = 0; e < N_EXP; e++) if (e != i0 && p[e] > p[i1]) i1 = e;
        int p0 = atomicAdd(&g_cnt[i0], 1);
        g_tok[i0 * N_TOK + p0] = n;  g_gw[i0 * N_TOK + p0] = p[i0];
        int p1 = atomicAdd(&g_cnt[i1], 1);
        g_tok[i1 * N_TOK + p1] = n;  g_gw[i1 * N_TOK + p1] = p[i1];
    }
}

__global__ void offsets_kernel() {
    if (threadIdx.x == 0 && blockIdx.x == 0) {
        int off = 0;
        for (int e = 0; e < N_EXP; e++) {
            g_off[e] = off;
            off += ((g_cnt[e] + BM - 1) / BM) * BM;
        }
    }
}

// ---------------------------------------------------------------------------
// GEMM core: 8 warps of 64x64, fp16 m16n8k16 with ldmatrix operands
// ---------------------------------------------------------------------------
#define DECLARE_TILE_CTX() \
    int tid = threadIdx.x, warp = tid >> 5, lane = tid & 31; \
    int gid = lane >> 2, tig = lane & 3; \
    int wm = (warp >> 2) * 64, wn = (warp & 3) * 64; \
    int t8 = lane & 7, ta = lane >> 3; \
    /* per-thread ldmatrix offsets (bytes, within stage) */ \
    uint32_t aoff = (uint32_t)(wm + (ta & 1) * 8 + t8) * (AH_STRIDE * 2) + (ta >> 1) * 16; \
    uint32_t boff = (uint32_t)((ta & 1) * 8 + t8) * (BH_STRIDE * 2) + (ta >> 1) * 16 + wn * 2; \
    float acc[4][8][4]; \
    _Pragma("unroll") for (int mf = 0; mf < 4; mf++) \
    _Pragma("unroll") for (int nf = 0; nf < 8; nf++) \
    _Pragma("unroll") for (int r = 0; r < 4; r++) acc[mf][nf][r] = 0.0f;

// one BK=32 k-tile = 2 x k16 steps
#define COMPUTE_KTILE(aBase, bBase) do { \
    _Pragma("unroll") \
    for (int ks = 0; ks < 2; ks++) { \
        uint32_t a[4][4], b[4][4]; \
        _Pragma("unroll") \
        for (int mf = 0; mf < 4; mf++) \
            LDSM_X4(a[mf], (aBase) + aoff + (uint32_t)mf * 16 * (AH_STRIDE * 2) + ks * 32); \
        _Pragma("unroll") \
        for (int p = 0; p < 4; p++) \
            LDSM_X4_T(b[p], (bBase) + boff + (uint32_t)p * 32 + (uint32_t)ks * 16 * (BH_STRIDE * 2)); \
        _Pragma("unroll") \
        for (int mf = 0; mf < 4; mf++) \
        _Pragma("unroll") \
        for (int nf = 0; nf < 8; nf++) \
            mma_f16(acc[mf][nf], a[mf][0], a[mf][1], a[mf][2], a[mf][3], \
                    b[nf >> 1][(nf & 1) * 2], b[nf >> 1][(nf & 1) * 2 + 1]); \
    } } while (0)

// ---------------------------------------------------------------------------
// ffn1: g_h = fp16(gelu(X_gathered @ W1[e] + b1[e]))   K = H_DIM
// ---------------------------------------------------------------------------
__global__ __launch_bounds__(NTHREADS, 1) void ffn1_kernel(const float* __restrict__ b1) {
    extern __shared__ char dsm[];
    int* toks = (int*)dsm;
    char* Asm = dsm + 512;
    char* Bsm = dsm + 512 + NSTAGE * A_STAGE_B;
    uint32_t As0 = (uint32_t)__cvta_generic_to_shared(Asm);
    uint32_t Bs0 = (uint32_t)__cvta_generic_to_shared(Bsm);

    int e    = blockIdx.y >> 5;
    int tile = blockIdx.y & 31;
    int row0 = tile * BM;
    int cnt  = g_cnt[e];
    if (row0 >= cnt) return;
    int off  = g_off[e];
    int col0 = blockIdx.x * BN;
    const __half* B = g_W1h + (size_t)e * H_DIM * F_DIM;

    DECLARE_TILE_CTX();

    if (tid < BM) {
        int r = row0 + tid; if (r >= cnt) r = cnt - 1;
        toks[tid] = g_tok[e * N_TOK + r];
    }
    __syncthreads();

    // cp.async slots: A 512 16B-chunks (2/thread: 128 rows x 4), B 1024 (4/thread: 32 rows x 32)
    uint32_t a_dst[2]; const __half* a_src[2];
#pragma unroll
    for (int i = 0; i < 2; i++) {
        int q = tid + i * 256; int r = q >> 2, c = q & 3;
        a_dst[i] = As0 + (uint32_t)r * (AH_STRIDE * 2) + c * 16;
        a_src[i] = g_xh + (size_t)toks[r] * H_DIM + c * 8;
    }
    uint32_t b_dst[4]; const __half* b_src[4];
#pragma unroll
    for (int i = 0; i < 4; i++) {
        int q = tid + i * 256; int kk = q >> 5, c = q & 31;
        b_dst[i] = Bs0 + (uint32_t)kk * (BH_STRIDE * 2) + c * 16;
        b_src[i] = B + (size_t)kk * F_DIM + col0 + c * 8;
    }

#define FILL1(st, ktile) do { \
    _Pragma("unroll") for (int i = 0; i < 2; i++) \
        CP_ASYNC16(a_dst[i] + (st) * A_STAGE_B, a_src[i] + (ktile) * BK); \
    _Pragma("unroll") for (int i = 0; i < 4; i++) \
        CP_ASYNC16(b_dst[i] + (st) * B_STAGE_B, b_src[i] + (size_t)(ktile) * BK * F_DIM); \
    CP_COMMIT(); } while (0)

    FILL1(0, 0);
    FILL1(1, 1);
    const int NKT = H_DIM / BK;
#pragma unroll 1
    for (int kt = 0; kt < NKT; kt++) {
        CP_WAIT1();
        __syncthreads();
        int nk = kt + 2;
        if (nk < NKT) FILL1(nk % NSTAGE, nk);
        int cs = kt % NSTAGE;
        COMPUTE_KTILE(As0 + cs * A_STAGE_B, Bs0 + cs * B_STAGE_B);
    }

    // epilogue: bias + exact gelu -> g_h (fp16)
#pragma unroll
    for (int mf = 0; mf < 4; mf++) {
#pragma unroll
        for (int r2 = 0; r2 < 2; r2++) {
            int m = wm + mf * 16 + gid + r2 * 8;
            __half* hrow = g_h + (size_t)(off + row0 + m) * F_DIM + col0;
#pragma unroll
            for (int nf = 0; nf < 8; nf++) {
                int c = wn + nf * 8 + tig * 2;
                float v0 = acc[mf][nf][r2 * 2 + 0] + b1[e * F_DIM + col0 + c];
                float v1 = acc[mf][nf][r2 * 2 + 1] + b1[e * F_DIM + col0 + c + 1];
                __half2 g = __floats2half2_rn(gelu_exact(v0), gelu_exact(v1));
                *reinterpret_cast<uint32_t*>(hrow + c) = *reinterpret_cast<uint32_t*>(&g);
            }
        }
    }
}

// ---------------------------------------------------------------------------
// ffn2: out[token] += gw * (h @ W2[e] + b2[e])   K = F_DIM
// ---------------------------------------------------------------------------
__global__ __launch_bounds__(NTHREADS, 1) void ffn2_kernel(
    const float* __restrict__ b2, float* __restrict__ out) {
    extern __shared__ char dsm[];
    char* Asm = dsm + 512;
    char* Bsm = dsm + 512 + NSTAGE * A_STAGE_B;
    uint32_t As0 = (uint32_t)__cvta_generic_to_shared(Asm);
    uint32_t Bs0 = (uint32_t)__cvta_generic_to_shared(Bsm);

    int e    = blockIdx.y >> 5;
    int tile = blockIdx.y & 31;
    int row0 = tile * BM;
    int cnt  = g_cnt[e];
    if (row0 >= cnt) return;
    int off  = g_off[e];
    int col0 = blockIdx.x * BN;
    const __half* B = g_W2h + (size_t)e * F_DIM * H_DIM;
    const __half* A = g_h + (size_t)(off + row0) * F_DIM;

    DECLARE_TILE_CTX();

    uint32_t a_dst[2]; const __half* a_src[2];
#pragma unroll
    for (int i = 0; i < 2; i++) {
        int q = tid + i * 256; int r = q >> 2, c = q & 3;
        a_dst[i] = As0 + (uint32_t)r * (AH_STRIDE * 2) + c * 16;
        a_src[i] = A + (size_t)r * F_DIM + c * 8;
    }
    uint32_t b_dst[4]; const __half* b_src[4];
#pragma unroll
    for (int i = 0; i < 4; i++) {
        int q = tid + i * 256; int kk = q >> 5, c = q & 31;
        b_dst[i] = Bs0 + (uint32_t)kk * (BH_STRIDE * 2) + c * 16;
        b_src[i] = B + (size_t)kk * H_DIM + col0 + c * 8;
    }

#define FILL2(st, ktile) do { \
    _Pragma("unroll") for (int i = 0; i < 2; i++) \
        CP_ASYNC16(a_dst[i] + (st) * A_STAGE_B, a_src[i] + (ktile) * BK); \
    _Pragma("unroll") for (int i = 0; i < 4; i++) \
        CP_ASYNC16(b_dst[i] + (st) * B_STAGE_B, b_src[i] + (size_t)(ktile) * BK * H_DIM); \
    CP_COMMIT(); } while (0)

    FILL2(0, 0);
    FILL2(1, 1);
    const int NKT = F_DIM / BK;
#pragma unroll 1
    for (int kt = 0; kt < NKT; kt++) {
        CP_WAIT1();
        __syncthreads();
        int nk = kt + 2;
        if (nk < NKT) FILL2(nk % NSTAGE, nk);
        int cs = kt % NSTAGE;
        COMPUTE_KTILE(As0 + cs * A_STAGE_B, Bs0 + cs * B_STAGE_B);
    }

    // epilogue: bias, gate weight, atomic scatter
#pragma unroll
    for (int mf = 0; mf < 4; mf++) {
#pragma unroll
        for (int r2 = 0; r2 < 2; r2++) {
            int m = wm + mf * 16 + gid + r2 * 8;
            int r = row0 + m;
            if (r < cnt) {
                int   token = g_tok[e * N_TOK + r];
                float gw    = g_gw [e * N_TOK + r];
                float* orow = out + (size_t)token * H_DIM + col0;
#pragma unroll
                for (int nf = 0; nf < 8; nf++) {
                    int c = wn + nf * 8 + tig * 2;
                    float v0 = acc[mf][nf][r2 * 2 + 0] + b2[e * H_DIM + col0 + c];
                    float v1 = acc[mf][nf][r2 * 2 + 1] + b2[e * H_DIM + col0 + c + 1];
                    atomicAdd(orow + c,     gw * v0);
                    atomicAdd(orow + c + 1, gw * v1);
                }
            }
        }
    }
}

extern "C" void kernel_launch(void* const* d_in, const int* in_sizes, int n_in,
                              void* d_out, int out_size) {
    const float* x  = (const float*)d_in[0];
    const float* W1 = (const float*)d_in[1];
    const float* b1 = (const float*)d_in[2];
    const float* W2 = (const float*)d_in[3];
    const float* b2 = (const float*)d_in[4];
    const float* Wg = (const float*)d_in[5];
    const float* bg = (const float*)d_in[6];
    float* out = (float*)d_out;

    cudaFuncSetAttribute(ffn1_kernel, cudaFuncAttributeMaxDynamicSharedMemorySize, SMEM_BYTES);
    cudaFuncSetAttribute(ffn2_kernel, cudaFuncAttributeMaxDynamicSharedMemorySize, SMEM_BYTES);

    __half* d_xh  = nullptr; cudaGetSymbolAddress((void**)&d_xh,  g_xh);
    __half* d_w1h = nullptr; cudaGetSymbolAddress((void**)&d_w1h, g_W1h);
    __half* d_w2h = nullptr; cudaGetSymbolAddress((void**)&d_w2h, g_W2h);

    zero_kernel<<<1024, 256>>>(out, out_size);
    h16conv_kernel<<<(N_TOK * H_DIM / 4) / 256, 256>>>(x, d_xh);
    h16conv_kernel<<<(N_EXP * H_DIM * F_DIM / 4) / 256, 256>>>(W1, d_w1h);
    h16conv_kernel<<<(N_EXP * H_DIM * F_DIM / 4) / 256, 256>>>(W2, d_w2h);
    gate_kernel<<<N_TOK / 8, 256>>>(x, Wg, bg);
    offsets_kernel<<<1, 1>>>();
    ffn1_kernel<<<dim3(F_DIM / BN, N_EXP * TILES_PER_E), NTHREADS, SMEM_BYTES>>>(b1);
    ffn2_kernel<<<dim3(H_DIM / BN, N_EXP * TILES_PER_E), NTHREADS, SMEM_BYTES>>>(b2, out);
}

// round 10
// speedup vs baseline: 1.6862x; 1.1016x over previous
#include <cuda_runtime.h>
#include <cuda_fp16.h>
#include <math.h>
#include <stdint.h>

#define N_TOK 4096
#define H_DIM 1024
#define F_DIM 4096
#define N_EXP 8

#define BM 128
#define BN 256
#define BK 64
#define NTHREADS 256
#define NSTAGE 3
#define TILES_PER_E 32

#define AH_STRIDE 72      // halfs: 64+8 pad -> 144B rows; seg = 9r mod 8 = r distinct
#define BH_STRIDE 264     // halfs: 256+8 pad -> 528B rows; seg = 33k mod 8 = k distinct
#define A_STAGE_B (BM * AH_STRIDE * 2)   // 18432 B
#define B_STAGE_B (BK * BH_STRIDE * 2)   // 33792 B
#define SMEM_BYTES (512 + NSTAGE * (A_STAGE_B + B_STAGE_B))   // 157184

#define WSZ ((size_t)N_EXP * H_DIM * F_DIM)

// Routing state + scratch (allocation-free: __device__ globals).
__device__ int    g_cnt[N_EXP];
__device__ int    g_off[N_EXP];
__device__ int    g_tok[N_EXP * N_TOK];
__device__ float  g_gw [N_EXP * N_TOK];
__device__ __half g_xh [(size_t)N_TOK * H_DIM];               // x  fp16
__device__ __half g_W1h[WSZ];                                  // W1 fp16 [E][H][F]
__device__ __half g_W2h[WSZ];                                  // W2 fp16 [E][F][H]
__device__ __half g_h  [(size_t)9216 * F_DIM];                // gelu(h) fp16

__device__ __forceinline__ void mma_f16(float c[4],
                                        uint32_t a0, uint32_t a1, uint32_t a2, uint32_t a3,
                                        uint32_t b0, uint32_t b1) {
    asm volatile(
        "mma.sync.aligned.m16n8k16.row.col.f32.f16.f16.f32 "
        "{%0,%1,%2,%3}, {%4,%5,%6,%7}, {%8,%9}, {%0,%1,%2,%3};\n"
        : "+f"(c[0]), "+f"(c[1]), "+f"(c[2]), "+f"(c[3])
        : "r"(a0), "r"(a1), "r"(a2), "r"(a3), "r"(b0), "r"(b1));
}
#define LDSM_X4(r, addr) \
    asm volatile("ldmatrix.sync.aligned.m8n8.x4.shared.b16 {%0,%1,%2,%3}, [%4];" \
        : "=r"((r)[0]), "=r"((r)[1]), "=r"((r)[2]), "=r"((r)[3]) : "r"(addr))
#define LDSM_X4_T(r, addr) \
    asm volatile("ldmatrix.sync.aligned.m8n8.x4.trans.shared.b16 {%0,%1,%2,%3}, [%4];" \
        : "=r"((r)[0]), "=r"((r)[1]), "=r"((r)[2]), "=r"((r)[3]) : "r"(addr))
#define CP_ASYNC16(dst, src) \
    asm volatile("cp.async.cg.shared.global [%0], [%1], 16;" :: "r"(dst), "l"(src) : "memory")
#define CP_COMMIT() asm volatile("cp.async.commit_group;" ::: "memory")
#define CP_WAIT1()  asm volatile("cp.async.wait_group 1;" ::: "memory")

__device__ __forceinline__ float gelu_exact(float v) {
    return 0.5f * v * (1.0f + erff(v * 0.70710678118654752f));
}

// ---------------- small kernels ----------------
__global__ void zero_kernel(float* __restrict__ out, int n) {
    int i = blockIdx.x * blockDim.x + threadIdx.x;
    if (i < N_EXP) g_cnt[i] = 0;
    int stride = gridDim.x * blockDim.x;
    for (int j = i; j < n; j += stride) out[j] = 0.0f;
}

__global__ void xconv_kernel(const float* __restrict__ x) {
    size_t i = (size_t)blockIdx.x * blockDim.x + threadIdx.x;
    float4 v = reinterpret_cast<const float4*>(x)[i];
    __half2 h0 = __floats2half2_rn(v.x, v.y);
    __half2 h1 = __floats2half2_rn(v.z, v.w);
    uint2 o = {*reinterpret_cast<uint32_t*>(&h0), *reinterpret_cast<uint32_t*>(&h1)};
    reinterpret_cast<uint2*>(g_xh)[i] = o;
}

// fused W1+W2 fp32->fp16 conversion, 4 elems/thread
__global__ void wconv_kernel(const float* __restrict__ W1, const float* __restrict__ W2) {
    size_t i = (size_t)blockIdx.x * blockDim.x + threadIdx.x;
    size_t half_n = WSZ / 4;
    const float4* src;
    uint2* dst;
    if (i < half_n) {
        src = reinterpret_cast<const float4*>(W1) + i;
        dst = reinterpret_cast<uint2*>(g_W1h) + i;
    } else {
        src = reinterpret_cast<const float4*>(W2) + (i - half_n);
        dst = reinterpret_cast<uint2*>(g_W2h) + (i - half_n);
    }
    float4 v = *src;
    __half2 h0 = __floats2half2_rn(v.x, v.y);
    __half2 h1 = __floats2half2_rn(v.z, v.w);
    uint2 o = {*reinterpret_cast<uint32_t*>(&h0), *reinterpret_cast<uint32_t*>(&h1)};
    *dst = o;
}

__global__ void gate_kernel(const float* __restrict__ x,
                            const float* __restrict__ Wg,
                            const float* __restrict__ bg) {
    int warp = threadIdx.x >> 5, lane = threadIdx.x & 31;
    int n = blockIdx.x * (blockDim.x >> 5) + warp;
    if (n >= N_TOK) return;
    float acc[N_EXP];
#pragma unroll
    for (int e = 0; e < N_EXP; e++) acc[e] = 0.0f;
    const float* xr = x + (size_t)n * H_DIM;
    for (int h = lane; h < H_DIM; h += 32) {
        float xv = xr[h];
        const float4 w0 = *reinterpret_cast<const float4*>(Wg + h * N_EXP);
        const float4 w1 = *reinterpret_cast<const float4*>(Wg + h * N_EXP + 4);
        acc[0] += xv * w0.x; acc[1] += xv * w0.y; acc[2] += xv * w0.z; acc[3] += xv * w0.w;
        acc[4] += xv * w1.x; acc[5] += xv * w1.y; acc[6] += xv * w1.z; acc[7] += xv * w1.w;
    }
#pragma unroll
    for (int e = 0; e < N_EXP; e++)
#pragma unroll
        for (int o = 16; o > 0; o >>= 1) acc[e] += __shfl_xor_sync(0xffffffffu, acc[e], o);
    if (lane == 0) {
        float p[N_EXP], m = -1e30f, s = 0.0f;
#pragma unroll
        for (int e = 0; e < N_EXP; e++) { p[e] = acc[e] + bg[e]; m = fmaxf(m, p[e]); }
#pragma unroll
        for (int e = 0; e < N_EXP; e++) { p[e] = expf(p[e] - m); s += p[e]; }
        float inv = 1.0f / s;
#pragma unroll
        for (int e = 0; e < N_EXP; e++) p[e] *= inv;
        int i0 = 0;
#pragma unroll
        for (int e = 1; e < N_EXP; e++) if (p[e] > p[i0]) i0 = e;
        int i1 = (i0 == 0) ? 1 : 0;
#pragma unroll
        for (int e = 0; e < N_EXP; e++) if (e != i0 && p[e] > p[i1]) i1 = e;
        int p0 = atomicAdd(&g_cnt[i0], 1);
        g_tok[i0 * N_TOK + p0] = n;  g_gw[i0 * N_TOK + p0] = p[i0];
        int p1 = atomicAdd(&g_cnt[i1], 1);
        g_tok[i1 * N_TOK + p1] = n;  g_gw[i1 * N_TOK + p1] = p[i1];
    }
}

__global__ void offsets_kernel() {
    if (threadIdx.x == 0 && blockIdx.x == 0) {
        int off = 0;
        for (int e = 0; e < N_EXP; e++) {
            g_off[e] = off;
            off += ((g_cnt[e] + BM - 1) / BM) * BM;
        }
    }
}

// ---------------------------------------------------------------------------
// GEMM core: 8 warps of 64x64, fp16 m16n8k16, ldmatrix operands, BK=64
// ---------------------------------------------------------------------------
#define DECLARE_TILE_CTX() \
    int tid = threadIdx.x, warp = tid >> 5, lane = tid & 31; \
    int gid = lane >> 2, tig = lane & 3; \
    int wm = (warp >> 2) * 64, wn = (warp & 3) * 64; \
    int t8 = lane & 7, ta = lane >> 3; \
    uint32_t aoff = (uint32_t)(wm + (ta & 1) * 8 + t8) * (AH_STRIDE * 2) + (ta >> 1) * 16; \
    uint32_t boff = (uint32_t)((ta & 1) * 8 + t8) * (BH_STRIDE * 2) + (ta >> 1) * 16 + wn * 2; \
    float acc[4][8][4]; \
    _Pragma("unroll") for (int mf = 0; mf < 4; mf++) \
    _Pragma("unroll") for (int nf = 0; nf < 8; nf++) \
    _Pragma("unroll") for (int r = 0; r < 4; r++) acc[mf][nf][r] = 0.0f;

// one BK=64 k-tile = 4 x k16 steps
#define COMPUTE_KTILE(aBase, bBase) do { \
    _Pragma("unroll") \
    for (int ks = 0; ks < 4; ks++) { \
        uint32_t a[4][4], b[4][4]; \
        _Pragma("unroll") \
        for (int mf = 0; mf < 4; mf++) \
            LDSM_X4(a[mf], (aBase) + aoff + (uint32_t)mf * 16 * (AH_STRIDE * 2) + ks * 32); \
        _Pragma("unroll") \
        for (int p = 0; p < 4; p++) \
            LDSM_X4_T(b[p], (bBase) + boff + (uint32_t)p * 32 + (uint32_t)ks * 16 * (BH_STRIDE * 2)); \
        _Pragma("unroll") \
        for (int mf = 0; mf < 4; mf++) \
        _Pragma("unroll") \
        for (int nf = 0; nf < 8; nf++) \
            mma_f16(acc[mf][nf], a[mf][0], a[mf][1], a[mf][2], a[mf][3], \
                    b[nf >> 1][(nf & 1) * 2], b[nf >> 1][(nf & 1) * 2 + 1]); \
    } } while (0)

// ---------------------------------------------------------------------------
// ffn1: g_h = fp16(gelu(X_gathered @ W1[e] + b1[e]))   K = H_DIM
// ---------------------------------------------------------------------------
__global__ __launch_bounds__(NTHREADS, 1) void ffn1_kernel(const float* __restrict__ b1) {
    extern __shared__ char dsm[];
    int* toks = (int*)dsm;
    uint32_t As0 = (uint32_t)__cvta_generic_to_shared(dsm + 512);
    uint32_t Bs0 = (uint32_t)__cvta_generic_to_shared(dsm + 512 + NSTAGE * A_STAGE_B);

    int e    = blockIdx.y >> 5;
    int tile = blockIdx.y & 31;
    int row0 = tile * BM;
    int cnt  = g_cnt[e];
    if (row0 >= cnt) return;
    int off  = g_off[e];
    int col0 = blockIdx.x * BN;
    const __half* B = g_W1h + (size_t)e * H_DIM * F_DIM;

    DECLARE_TILE_CTX();

    if (tid < BM) {
        int r = row0 + tid; if (r >= cnt) r = cnt - 1;
        toks[tid] = g_tok[e * N_TOK + r];
    }
    __syncthreads();

    // cp.async: A 1024 16B-chunks (4/thread: 128 rows x 8), B 2048 (8/thread: 64 rows x 32)
    uint32_t a_dst[4]; const __half* a_src[4];
#pragma unroll
    for (int i = 0; i < 4; i++) {
        int q = tid + i * 256; int r = q >> 3, c = q & 7;
        a_dst[i] = As0 + (uint32_t)r * (AH_STRIDE * 2) + c * 16;
        a_src[i] = g_xh + (size_t)toks[r] * H_DIM + c * 8;
    }
    uint32_t b_dst[8]; const __half* b_src[8];
#pragma unroll
    for (int i = 0; i < 8; i++) {
        int q = tid + i * 256; int kk = q >> 5, c = q & 31;
        b_dst[i] = Bs0 + (uint32_t)kk * (BH_STRIDE * 2) + c * 16;
        b_src[i] = B + (size_t)kk * F_DIM + col0 + c * 8;
    }

#define FILL1(st, ktile) do { \
    _Pragma("unroll") for (int i = 0; i < 4; i++) \
        CP_ASYNC16(a_dst[i] + (st) * A_STAGE_B, a_src[i] + (ktile) * BK); \
    _Pragma("unroll") for (int i = 0; i < 8; i++) \
        CP_ASYNC16(b_dst[i] + (st) * B_STAGE_B, b_src[i] + (size_t)(ktile) * BK * F_DIM); \
    CP_COMMIT(); } while (0)

    FILL1(0, 0);
    FILL1(1, 1);
    const int NKT = H_DIM / BK;
#pragma unroll 1
    for (int kt = 0; kt < NKT; kt++) {
        CP_WAIT1();
        __syncthreads();
        int nk = kt + 2;
        if (nk < NKT) FILL1(nk % NSTAGE, nk);
        int cs = kt % NSTAGE;
        COMPUTE_KTILE(As0 + cs * A_STAGE_B, Bs0 + cs * B_STAGE_B);
    }

    // epilogue: bias + exact gelu -> g_h (fp16)
#pragma unroll
    for (int mf = 0; mf < 4; mf++) {
#pragma unroll
        for (int r2 = 0; r2 < 2; r2++) {
            int m = wm + mf * 16 + gid + r2 * 8;
            __half* hrow = g_h + (size_t)(off + row0 + m) * F_DIM + col0;
#pragma unroll
            for (int nf = 0; nf < 8; nf++) {
                int c = wn + nf * 8 + tig * 2;
                float v0 = acc[mf][nf][r2 * 2 + 0] + b1[e * F_DIM + col0 + c];
                float v1 = acc[mf][nf][r2 * 2 + 1] + b1[e * F_DIM + col0 + c + 1];
                __half2 g = __floats2half2_rn(gelu_exact(v0), gelu_exact(v1));
                *reinterpret_cast<uint32_t*>(hrow + c) = *reinterpret_cast<uint32_t*>(&g);
            }
        }
    }
}

// ---------------------------------------------------------------------------
// ffn2: out[token] += gw * (h @ W2[e] + b2[e])   K = F_DIM
// ---------------------------------------------------------------------------
__global__ __launch_bounds__(NTHREADS, 1) void ffn2_kernel(
    const float* __restrict__ b2, float* __restrict__ out) {
    extern __shared__ char dsm[];
    uint32_t As0 = (uint32_t)__cvta_generic_to_shared(dsm + 512);
    uint32_t Bs0 = (uint32_t)__cvta_generic_to_shared(dsm + 512 + NSTAGE * A_STAGE_B);

    int e    = blockIdx.y >> 5;
    int tile = blockIdx.y & 31;
    int row0 = tile * BM;
    int cnt  = g_cnt[e];
    if (row0 >= cnt) return;
    int off  = g_off[e];
    int col0 = blockIdx.x * BN;
    const __half* B = g_W2h + (size_t)e * F_DIM * H_DIM;
    const __half* A = g_h + (size_t)(off + row0) * F_DIM;

    DECLARE_TILE_CTX();

    uint32_t a_dst[4]; const __half* a_src[4];
#pragma unroll
    for (int i = 0; i < 4; i++) {
        int q = tid + i * 256; int r = q >> 3, c = q & 7;
        a_dst[i] = As0 + (uint32_t)r * (AH_STRIDE * 2) + c * 16;
        a_src[i] = A + (size_t)r * F_DIM + c * 8;
    }
    uint32_t b_dst[8]; const __half* b_src[8];
#pragma unroll
    for (int i = 0; i < 8; i++) {
        int q = tid + i * 256; int kk = q >> 5, c = q & 31;
        b_dst[i] = Bs0 + (uint32_t)kk * (BH_STRIDE * 2) + c * 16;
        b_src[i] = B + (size_t)kk * H_DIM + col0 + c * 8;
    }

#define FILL2(st, ktile) do { \
    _Pragma("unroll") for (int i = 0; i < 4; i++) \
        CP_ASYNC16(a_dst[i] + (st) * A_STAGE_B, a_src[i] + (ktile) * BK); \
    _Pragma("unroll") for (int i = 0; i < 8; i++) \
        CP_ASYNC16(b_dst[i] + (st) * B_STAGE_B, b_src[i] + (size_t)(ktile) * BK * H_DIM); \
    CP_COMMIT(); } while (0)

    FILL2(0, 0);
    FILL2(1, 1);
    const int NKT = F_DIM / BK;
#pragma unroll 1
    for (int kt = 0; kt < NKT; kt++) {
        CP_WAIT1();
        __syncthreads();
        int nk = kt + 2;
        if (nk < NKT) FILL2(nk % NSTAGE, nk);
        int cs = kt % NSTAGE;
        COMPUTE_KTILE(As0 + cs * A_STAGE_B, Bs0 + cs * B_STAGE_B);
    }

    // epilogue: bias, gate weight, atomic scatter
#pragma unroll
    for (int mf = 0; mf < 4; mf++) {
#pragma unroll
        for (int r2 = 0; r2 < 2; r2++) {
            int m = wm + mf * 16 + gid + r2 * 8;
            int r = row0 + m;
            if (r < cnt) {
                int   token = g_tok[e * N_TOK + r];
                float gw    = g_gw [e * N_TOK + r];
                float* orow = out + (size_t)token * H_DIM + col0;
#pragma unroll
                for (int nf = 0; nf < 8; nf++) {
                    int c = wn + nf * 8 + tig * 2;
                    float v0 = acc[mf][nf][r2 * 2 + 0] + b2[e * H_DIM + col0 + c];
                    float v1 = acc[mf][nf][r2 * 2 + 1] + b2[e * H_DIM + col0 + c + 1];
                    atomicAdd(orow + c,     gw * v0);
                    atomicAdd(orow + c + 1, gw * v1);
                }
            }
        }
    }
}

extern "C" void kernel_launch(void* const* d_in, const int* in_sizes, int n_in,
                              void* d_out, int out_size) {
    const float* x  = (const float*)d_in[0];
    const float* W1 = (const float*)d_in[1];
    const float* b1 = (const float*)d_in[2];
    const float* W2 = (const float*)d_in[3];
    const float* b2 = (const float*)d_in[4];
    const float* Wg = (const float*)d_in[5];
    const float* bg = (const float*)d_in[6];
    float* out = (float*)d_out;

    cudaFuncSetAttribute(ffn1_kernel, cudaFuncAttributeMaxDynamicSharedMemorySize, SMEM_BYTES);
    cudaFuncSetAttribute(ffn2_kernel, cudaFuncAttributeMaxDynamicSharedMemorySize, SMEM_BYTES);

    zero_kernel<<<1024, 256>>>(out, out_size);
    gate_kernel<<<N_TOK / 8, 256>>>(x, Wg, bg);
    offsets_kernel<<<1, 1>>>();
    xconv_kernel<<<(N_TOK * H_DIM / 4) / 256, 256>>>(x);
    wconv_kernel<<<(2 * WSZ / 4) / 256, 256>>>(W1, W2);
    ffn1_kernel<<<dim3(F_DIM / BN, N_EXP * TILES_PER_E), NTHREADS, SMEM_BYTES>>>(b1);
    ffn2_kernel<<<dim3(H_DIM / BN, N_EXP * TILES_PER_E), NTHREADS, SMEM_BYTES>>>(b2, out);
}